// round 6
// baseline (speedup 1.0000x reference)
#include <cuda_runtime.h>
#include <math.h>

// Problem constants
#define B_ 4
#define CIN_ 128
#define COUT_ 128
#define H_ 128
#define W_ 128
#define HW_ (H_*W_)
#define KK_ 9
#define CK_ (KK_*CIN_)   // 1152

// Scratch (device globals; no allocation allowed)
__device__ float g_nhwc[B_*HW_*CIN_];          // inp transposed to NHWC
__device__ float g_wq[COUT_*CK_];              // w_dc reordered: [(ck>>2)][oc][ck&3]
__device__ float g_py[B_*KK_*HW_];             // absolute sample y
__device__ float g_px[B_*KK_*HW_];             // absolute sample x
__device__ float g_m [B_*KK_*HW_];             // sigmoid mask

// ---------------------------------------------------------------------------
// Kernel 1: NCHW -> NHWC transpose of inp (per b: [C][HW] -> [HW][C])
// ---------------------------------------------------------------------------
__global__ void k_transpose(const float* __restrict__ inp) {
    __shared__ float tile[32][33];
    int b  = blockIdx.z;
    int c0 = blockIdx.y * 32;
    int h0 = blockIdx.x * 32;
    int tx = threadIdx.x, ty = threadIdx.y;
    #pragma unroll
    for (int i = 0; i < 4; ++i) {
        int c = c0 + ty + 8*i;
        tile[ty + 8*i][tx] = inp[(b*CIN_ + c)*HW_ + h0 + tx];
    }
    __syncthreads();
    #pragma unroll
    for (int i = 0; i < 4; ++i) {
        int hw = h0 + ty + 8*i;
        g_nhwc[(b*HW_ + hw)*CIN_ + c0 + tx] = tile[tx][ty + 8*i];
    }
}

// ---------------------------------------------------------------------------
// Kernel 2: reorder w_dc[oc][c][k] -> g_wq[(k*128+c)>>2][oc][(k*128+c)&3]
// ck = k*128 + c.  g_wq flat index = ckq*512 + oc*4 + r
// ---------------------------------------------------------------------------
__global__ void k_wprep(const float* __restrict__ w_dc) {
    int t = blockIdx.x * blockDim.x + threadIdx.x;
    if (t >= COUT_*CK_) return;
    int oc = t / CK_;
    int r  = t % CK_;
    int c  = r / KK_;
    int k  = r % KK_;
    int ck = k*CIN_ + c;
    g_wq[(ck >> 2)*512 + oc*4 + (ck & 3)] = w_dc[t];
}

// ---------------------------------------------------------------------------
// Kernel 3: offset conv (27 channels) + positions/masks
// block = 2 rows x 128 cols, 256 threads, 1 pixel per thread (27 accumulators)
// ---------------------------------------------------------------------------
__global__ void __launch_bounds__(256) k_offconv(const float* __restrict__ feat,
                                                 const float* __restrict__ w_off,
                                                 const float* __restrict__ b_off) {
    __shared__ float ws[32*9*28];   // 32 c-chunk, 9 taps, 27 oc (+1 pad) = 32.25KB
    int tid = threadIdx.x;
    int b = blockIdx.x >> 6;
    int y = ((blockIdx.x & 63) << 1) + (tid >> 7);
    int x = tid & 127;

    float acc[28];
    #pragma unroll
    for (int i = 0; i < 28; ++i) acc[i] = 0.f;

    for (int cc = 0; cc < 4; ++cc) {
        __syncthreads();
        // load weights for this c-chunk: ws[(cl*9+k)*28 + oc]
        for (int e = tid; e < 32*9*27; e += 256) {
            int oc = e % 27;
            int t2 = e / 27;
            int k  = t2 % 9;
            int cl = t2 / 9;
            ws[(cl*9+k)*28 + oc] = w_off[(oc*CIN_ + (cc*32 + cl))*KK_ + k];
        }
        for (int e = tid; e < 32*9; e += 256) ws[e*28 + 27] = 0.f;
        __syncthreads();

        for (int cl = 0; cl < 32; ++cl) {
            int c = cc*32 + cl;
            const float* fb = feat + (b*CIN_ + c)*HW_;
            float f[9];
            #pragma unroll
            for (int r = 0; r < 3; ++r) {
                #pragma unroll
                for (int s = 0; s < 3; ++s) {
                    int yy = y - 1 + r, xx = x - 1 + s;
                    bool v = (yy >= 0) && (yy < H_) && (xx >= 0) && (xx < W_);
                    f[r*3+s] = v ? fb[yy*W_ + xx] : 0.f;
                }
            }
            #pragma unroll
            for (int k = 0; k < 9; ++k) {
                float v = f[k];
                const float4* w4p = (const float4*)(ws + (cl*9+k)*28);
                #pragma unroll
                for (int q = 0; q < 7; ++q) {
                    float4 w4 = w4p[q];
                    acc[q*4+0] = fmaf(v, w4.x, acc[q*4+0]);
                    acc[q*4+1] = fmaf(v, w4.y, acc[q*4+1]);
                    acc[q*4+2] = fmaf(v, w4.z, acc[q*4+2]);
                    acc[q*4+3] = fmaf(v, w4.w, acc[q*4+3]);
                }
            }
        }
    }
    #pragma unroll
    for (int oc = 0; oc < 27; ++oc) acc[oc] += b_off[oc];

    // per-tap positions + mask
    #pragma unroll
    for (int k = 0; k < 9; ++k) {
        float py = acc[2*k]     + (float)(y + (k/3) - 1);
        float px = acc[2*k + 1] + (float)(x + (k%3) - 1);
        float m  = 1.f / (1.f + expf(-acc[18 + k]));
        int idx = (b*KK_ + k)*HW_ + y*W_ + x;
        g_py[idx] = py;
        g_px[idx] = px;
        g_m[idx]  = m;
    }
}

// ---------------------------------------------------------------------------
// Kernel 4: main deformable conv.
// Block = 32 pixels of one row (b, y, x0..x0+31), 256 threads.
// Phase1: corner indices/weights.  Phase2: gather val[1152][32] into shared.
// Phase3: GEMM out[32][128] = val^T * w  with w streamed in 48KB chunks.
// ---------------------------------------------------------------------------
__global__ void __launch_bounds__(256) k_dcn(const float* __restrict__ b_dc,
                                             float* __restrict__ out) {
    extern __shared__ float smem[];
    float* val_s = smem;                                  // 1152*32 floats
    float* w_s   = smem + CK_*32;                         // 96*128 floats
    int*   cb_s  = (int*)  (smem + CK_*32 + 96*128);      // 288*4 ints
    float* cw_s  = (float*)(cb_s + 288*4);                // 288*4 floats

    int tid = threadIdx.x;
    int blk = blockIdx.x;
    int b  = blk >> 9;
    int y  = (blk >> 2) & 127;
    int x0 = (blk & 3) << 5;

    // ---- Phase 1: corner bases + combined weights for 288 (tap,pixel) ----
    for (int kp = tid; kp < 288; kp += 256) {
        int k = kp >> 5, p = kp & 31;
        int x = x0 + p;
        int idx = (b*KK_ + k)*HW_ + y*W_ + x;
        float py = g_py[idx], px = g_px[idx], m = g_m[idx];
        float y0f = floorf(py), x0f = floorf(px);
        float ly = py - y0f, lx = px - x0f;
        // clamp in float domain first to avoid int overflow on crazy offsets
        y0f = fminf(fmaxf(y0f, -4.f), 132.f);
        x0f = fminf(fmaxf(x0f, -4.f), 132.f);
        int yi = (int)y0f, xi = (int)x0f;
        float wgt[4] = {(1.f-ly)*(1.f-lx), (1.f-ly)*lx, ly*(1.f-lx), ly*lx};
        int dy[4] = {0,0,1,1};
        int dx[4] = {0,1,0,1};
        #pragma unroll
        for (int j = 0; j < 4; ++j) {
            int yy = yi + dy[j], xx = xi + dx[j];
            bool v = (yy >= 0) && (yy < H_) && (xx >= 0) && (xx < W_);
            int yc = min(max(yy, 0), H_-1);
            int xc = min(max(xx, 0), W_-1);
            cb_s[kp*4 + j] = ((b*H_ + yc)*W_ + xc) * CIN_;
            cw_s[kp*4 + j] = v ? wgt[j]*m : 0.f;
        }
    }
    __syncthreads();

    // ---- Phase 2: gather val[ck][p], ck = k*128 + c ----
    // tasks: cg (32 c-quads) x 288 (kp).  Lanes span kp -> STS conflict-free.
    #pragma unroll 2
    for (int it = 0; it < 36; ++it) {
        int task = tid + (it << 8);
        int cg = task / 288;
        int kp = task - cg*288;
        int k = kp >> 5, p = kp & 31;
        float ax = 0.f, ay = 0.f, az = 0.f, aw = 0.f;
        #pragma unroll
        for (int j = 0; j < 4; ++j) {
            int base = cb_s[kp*4 + j];
            float w = cw_s[kp*4 + j];
            float4 t = *(const float4*)(g_nhwc + base + (cg << 2));
            ax = fmaf(w, t.x, ax);
            ay = fmaf(w, t.y, ay);
            az = fmaf(w, t.z, az);
            aw = fmaf(w, t.w, aw);
        }
        int ck = (k << 7) + (cg << 2);
        val_s[(ck+0)*32 + p] = ax;
        val_s[(ck+1)*32 + p] = ay;
        val_s[(ck+2)*32 + p] = az;
        val_s[(ck+3)*32 + p] = aw;
    }

    // ---- Phase 3: GEMM ----
    int p   = tid & 31;
    int oc0 = (tid >> 5) << 4;    // 8 groups x 16 oc
    float acc[16];
    #pragma unroll
    for (int j = 0; j < 16; ++j) acc[j] = 0.f;

    for (int chunk = 0; chunk < 12; ++chunk) {
        __syncthreads();
        // stage w chunk: contiguous 48KB memcpy (layout pre-arranged by k_wprep)
        const float4* src = (const float4*)(g_wq + chunk*96*COUT_);
        float4* dst = (float4*)w_s;
        #pragma unroll
        for (int i = 0; i < 12; ++i) dst[tid + (i << 8)] = src[tid + (i << 8)];
        __syncthreads();

        int ckb = chunk * 96;
        const float4* ws4 = (const float4*)w_s;
        #pragma unroll 4
        for (int q = 0; q < 24; ++q) {
            int ck = ckb + (q << 2);
            float v0 = val_s[(ck+0)*32 + p];
            float v1 = val_s[(ck+1)*32 + p];
            float v2 = val_s[(ck+2)*32 + p];
            float v3 = val_s[(ck+3)*32 + p];
            const float4* wrow = ws4 + (q << 7) + oc0;
            #pragma unroll
            for (int j = 0; j < 16; ++j) {
                float4 w4 = wrow[j];
                acc[j] = fmaf(w4.x, v0, acc[j]);
                acc[j] = fmaf(w4.y, v1, acc[j]);
                acc[j] = fmaf(w4.z, v2, acc[j]);
                acc[j] = fmaf(w4.w, v3, acc[j]);
            }
        }
    }

    // ---- Epilogue: NCHW output, coalesced per oc (lanes = x) ----
    #pragma unroll
    for (int j = 0; j < 16; ++j) {
        int oc = oc0 + j;
        out[((b*COUT_ + oc)*H_ + y)*W_ + x0 + p] = acc[j] + b_dc[oc];
    }
}

// ---------------------------------------------------------------------------
extern "C" void kernel_launch(void* const* d_in, const int* in_sizes, int n_in,
                              void* d_out, int out_size) {
    const float* inp   = (const float*)d_in[0];
    const float* feat  = (const float*)d_in[1];
    const float* w_off = (const float*)d_in[2];
    const float* b_off = (const float*)d_in[3];
    const float* w_dc  = (const float*)d_in[4];
    const float* b_dc  = (const float*)d_in[5];
    float* out = (float*)d_out;

    const int dyn_smem = (CK_*32 + 96*COUT_)*4 + 288*4*4*2;  // 205824 B
    cudaFuncSetAttribute(k_dcn, cudaFuncAttributeMaxDynamicSharedMemorySize, dyn_smem);

    k_transpose<<<dim3(HW_/32, CIN_/32, B_), dim3(32, 8)>>>(inp);
    k_wprep<<<(COUT_*CK_ + 255)/256, 256>>>(w_dc);
    k_offconv<<<B_*(H_/2), 256>>>(feat, w_off, b_off);
    k_dcn<<<B_*H_*(W_/32), 256, dyn_smem>>>(b_dc, out);
}

// round 8
// speedup vs baseline: 1.4498x; 1.4498x over previous
#include <cuda_runtime.h>
#include <math.h>

// Problem constants
#define B_ 4
#define CIN_ 128
#define COUT_ 128
#define H_ 128
#define W_ 128
#define HW_ (H_*W_)
#define KK_ 9
#define CK_ (KK_*CIN_)   // 1152

// Scratch (device globals; no allocation allowed)
__device__ float g_nhwc[B_*HW_*CIN_];          // inp transposed to NHWC
__device__ float g_wt[CK_*COUT_];              // w_dc reordered: [ck][oc], ck=k*128+c
__device__ float g_py[B_*KK_*HW_];             // absolute sample y
__device__ float g_px[B_*KK_*HW_];             // absolute sample x
__device__ float g_m [B_*KK_*HW_];             // sigmoid mask

// ---------------------------------------------------------------------------
// Kernel 1: NCHW -> NHWC transpose of inp (per b: [C][HW] -> [HW][C])
// ---------------------------------------------------------------------------
__global__ void k_transpose(const float* __restrict__ inp) {
    __shared__ float tile[32][33];
    int b  = blockIdx.z;
    int c0 = blockIdx.y * 32;
    int h0 = blockIdx.x * 32;
    int tx = threadIdx.x, ty = threadIdx.y;
    #pragma unroll
    for (int i = 0; i < 4; ++i) {
        int c = c0 + ty + 8*i;
        tile[ty + 8*i][tx] = inp[(b*CIN_ + c)*HW_ + h0 + tx];
    }
    __syncthreads();
    #pragma unroll
    for (int i = 0; i < 4; ++i) {
        int hw = h0 + ty + 8*i;
        g_nhwc[(b*HW_ + hw)*CIN_ + c0 + tx] = tile[tx][ty + 8*i];
    }
}

// ---------------------------------------------------------------------------
// Kernel 2: reorder w_dc[oc][c][k] -> g_wt[(k*128+c)][oc]  (oc contiguous)
// ---------------------------------------------------------------------------
__global__ void k_wprep(const float* __restrict__ w_dc) {
    int t = blockIdx.x * blockDim.x + threadIdx.x;
    if (t >= COUT_*CK_) return;
    int oc = t / CK_;
    int r  = t % CK_;
    int c  = r / KK_;
    int k  = r % KK_;
    int ck = k*CIN_ + c;
    g_wt[ck*COUT_ + oc] = w_dc[t];
}

// ---------------------------------------------------------------------------
// Kernel 3: offset conv (27 channels) + positions/masks
// block = 2 rows x 128 cols, 256 threads, 1 pixel per thread (27 accumulators)
// ---------------------------------------------------------------------------
__global__ void __launch_bounds__(256) k_offconv(const float* __restrict__ feat,
                                                 const float* __restrict__ w_off,
                                                 const float* __restrict__ b_off) {
    __shared__ float ws[32*9*28];   // 32 c-chunk, 9 taps, 27 oc (+1 pad)
    int tid = threadIdx.x;
    int b = blockIdx.x >> 6;
    int y = ((blockIdx.x & 63) << 1) + (tid >> 7);
    int x = tid & 127;

    float acc[28];
    #pragma unroll
    for (int i = 0; i < 28; ++i) acc[i] = 0.f;

    for (int cc = 0; cc < 4; ++cc) {
        __syncthreads();
        for (int e = tid; e < 32*9*27; e += 256) {
            int oc = e % 27;
            int t2 = e / 27;
            int k  = t2 % 9;
            int cl = t2 / 9;
            ws[(cl*9+k)*28 + oc] = w_off[(oc*CIN_ + (cc*32 + cl))*KK_ + k];
        }
        for (int e = tid; e < 32*9; e += 256) ws[e*28 + 27] = 0.f;
        __syncthreads();

        for (int cl = 0; cl < 32; ++cl) {
            int c = cc*32 + cl;
            const float* fb = feat + (b*CIN_ + c)*HW_;
            float f[9];
            #pragma unroll
            for (int r = 0; r < 3; ++r) {
                #pragma unroll
                for (int s = 0; s < 3; ++s) {
                    int yy = y - 1 + r, xx = x - 1 + s;
                    bool v = (yy >= 0) && (yy < H_) && (xx >= 0) && (xx < W_);
                    f[r*3+s] = v ? fb[yy*W_ + xx] : 0.f;
                }
            }
            #pragma unroll
            for (int k = 0; k < 9; ++k) {
                float v = f[k];
                const float4* w4p = (const float4*)(ws + (cl*9+k)*28);
                #pragma unroll
                for (int q = 0; q < 7; ++q) {
                    float4 w4 = w4p[q];
                    acc[q*4+0] = fmaf(v, w4.x, acc[q*4+0]);
                    acc[q*4+1] = fmaf(v, w4.y, acc[q*4+1]);
                    acc[q*4+2] = fmaf(v, w4.z, acc[q*4+2]);
                    acc[q*4+3] = fmaf(v, w4.w, acc[q*4+3]);
                }
            }
        }
    }
    #pragma unroll
    for (int oc = 0; oc < 27; ++oc) acc[oc] += b_off[oc];

    #pragma unroll
    for (int k = 0; k < 9; ++k) {
        float py = acc[2*k]     + (float)(y + (k/3) - 1);
        float px = acc[2*k + 1] + (float)(x + (k%3) - 1);
        float m  = 1.f / (1.f + expf(-acc[18 + k]));
        int idx = (b*KK_ + k)*HW_ + y*W_ + x;
        g_py[idx] = py;
        g_px[idx] = px;
        g_m[idx]  = m;
    }
}

// ---------------------------------------------------------------------------
// Kernel 4: main deformable conv, v2.
// Block = 64 pixels of one row. 256 threads, 3 blocks/SM (67.6KB smem).
// K-dim processed in 18 chunks of 64 ck: stage w[64][128] + gather val[64][64]
// into shared, then FMA-dense GEMM (thread tile 8 oc x 4 px).
// ---------------------------------------------------------------------------
#define PX_ 64
#define CKC_ 64          // ck per chunk
#define NCHUNK_ 18

__global__ void __launch_bounds__(256, 3) k_dcn(const float* __restrict__ b_dc,
                                                float* __restrict__ out) {
    extern __shared__ float smem[];
    float* val_s = smem;                         // [64][64]   16KB
    float* w_s   = smem + CKC_*PX_;              // [64][128]  32KB
    int*   cb_s  = (int*)  (w_s + CKC_*COUT_);   // [9*64][4]  9.2KB
    float* cw_s  = (float*)(cb_s + 9*PX_*4);     // [9*64][4]  9.2KB

    int tid = threadIdx.x;
    int blk = blockIdx.x;
    int b  = blk >> 8;
    int y  = (blk >> 1) & 127;
    int x0 = (blk & 1) << 6;

    // ---- Phase 1: corner bases + combined weights for 9 taps x 64 px ----
    for (int kp = tid; kp < 9*PX_; kp += 256) {
        int k = kp >> 6, p = kp & 63;
        int x = x0 + p;
        int idx = (b*KK_ + k)*HW_ + y*W_ + x;
        float py = g_py[idx], px = g_px[idx], m = g_m[idx];
        float y0f = floorf(py), x0f = floorf(px);
        float ly = py - y0f, lx = px - x0f;
        y0f = fminf(fmaxf(y0f, -4.f), 132.f);
        x0f = fminf(fmaxf(x0f, -4.f), 132.f);
        int yi = (int)y0f, xi = (int)x0f;
        float wgt[4] = {(1.f-ly)*(1.f-lx), (1.f-ly)*lx, ly*(1.f-lx), ly*lx};
        const int dy[4] = {0,0,1,1};
        const int dx[4] = {0,1,0,1};
        #pragma unroll
        for (int j = 0; j < 4; ++j) {
            int yy = yi + dy[j], xx = xi + dx[j];
            bool v = (yy >= 0) && (yy < H_) && (xx >= 0) && (xx < W_);
            int yc = min(max(yy, 0), H_-1);
            int xc = min(max(xx, 0), W_-1);
            cb_s[kp*4 + j] = ((b*H_ + yc)*W_ + xc) * CIN_;
            cw_s[kp*4 + j] = v ? wgt[j]*m : 0.f;
        }
    }

    // GEMM thread tile: 8 oc x 4 px
    int px0 = (tid & 15) << 2;
    int oc0 = (tid >> 4) << 3;
    float acc[8][4];
    #pragma unroll
    for (int j = 0; j < 8; ++j)
        #pragma unroll
        for (int q = 0; q < 4; ++q) acc[j][q] = 0.f;

    // ---- Main loop over 18 K-chunks (tap k = chunk>>1, channels h*64..) ----
    for (int chunk = 0; chunk < NCHUNK_; ++chunk) {
        int k  = chunk >> 1;
        int c0 = (chunk & 1) << 6;
        __syncthreads();

        // stage weights: w_s[ckl][oc] <- g_wt[(chunk*64 + ckl)][oc], 32KB
        {
            const float4* src = (const float4*)(g_wt + chunk*CKC_*COUT_);
            float4* dst = (float4*)w_s;
            #pragma unroll
            for (int i = 0; i < 8; ++i) dst[tid + (i << 8)] = src[tid + (i << 8)];
        }

        // gather val_s[ckl][p]: 16 cg x 64 px tasks, 4 per thread
        #pragma unroll
        for (int i = 0; i < 4; ++i) {
            int t2 = tid + (i << 8);
            int cg = t2 >> 6;          // 0..15
            int p  = t2 & 63;
            const int*   cb = cb_s + ((k << 6) + p)*4;
            const float* cw = cw_s + ((k << 6) + p)*4;
            float ax = 0.f, ay = 0.f, az = 0.f, aw = 0.f;
            #pragma unroll
            for (int j = 0; j < 4; ++j) {
                float w = cw[j];
                float4 t = *(const float4*)(g_nhwc + cb[j] + c0 + (cg << 2));
                ax = fmaf(w, t.x, ax);
                ay = fmaf(w, t.y, ay);
                az = fmaf(w, t.z, az);
                aw = fmaf(w, t.w, aw);
            }
            int ckl = cg << 2;
            val_s[(ckl+0)*PX_ + p] = ax;
            val_s[(ckl+1)*PX_ + p] = ay;
            val_s[(ckl+2)*PX_ + p] = az;
            val_s[(ckl+3)*PX_ + p] = aw;
        }
        __syncthreads();

        // GEMM accumulate over this chunk's 64 ck
        #pragma unroll 8
        for (int ckl = 0; ckl < CKC_; ++ckl) {
            float4 v  = *(const float4*)(val_s + ckl*PX_ + px0);
            float4 wa = *(const float4*)(w_s + ckl*COUT_ + oc0);
            float4 wb = *(const float4*)(w_s + ckl*COUT_ + oc0 + 4);
            float wv[8] = {wa.x, wa.y, wa.z, wa.w, wb.x, wb.y, wb.z, wb.w};
            #pragma unroll
            for (int j = 0; j < 8; ++j) {
                acc[j][0] = fmaf(wv[j], v.x, acc[j][0]);
                acc[j][1] = fmaf(wv[j], v.y, acc[j][1]);
                acc[j][2] = fmaf(wv[j], v.z, acc[j][2]);
                acc[j][3] = fmaf(wv[j], v.w, acc[j][3]);
            }
        }
    }

    // ---- Epilogue: NCHW output, float4 per oc ----
    #pragma unroll
    for (int j = 0; j < 8; ++j) {
        int oc = oc0 + j;
        float bv = b_dc[oc];
        float4 o4 = make_float4(acc[j][0]+bv, acc[j][1]+bv, acc[j][2]+bv, acc[j][3]+bv);
        *(float4*)(out + ((b*COUT_ + oc)*H_ + y)*W_ + x0 + px0) = o4;
    }
}

// ---------------------------------------------------------------------------
extern "C" void kernel_launch(void* const* d_in, const int* in_sizes, int n_in,
                              void* d_out, int out_size) {
    const float* inp   = (const float*)d_in[0];
    const float* feat  = (const float*)d_in[1];
    const float* w_off = (const float*)d_in[2];
    const float* b_off = (const float*)d_in[3];
    const float* w_dc  = (const float*)d_in[4];
    const float* b_dc  = (const float*)d_in[5];
    float* out = (float*)d_out;

    const int dyn_smem = (CKC_*PX_ + CKC_*COUT_ + 9*PX_*4*2) * 4;  // 67584 B
    cudaFuncSetAttribute(k_dcn, cudaFuncAttributeMaxDynamicSharedMemorySize, dyn_smem);

    k_transpose<<<dim3(HW_/32, CIN_/32, B_), dim3(32, 8)>>>(inp);
    k_wprep<<<(COUT_*CK_ + 255)/256, 256>>>(w_dc);
    k_offconv<<<B_*(H_/2), 256>>>(feat, w_off, b_off);
    k_dcn<<<B_*H_*(W_/64), 256, dyn_smem>>>(b_dc, out);
}

// round 9
// speedup vs baseline: 1.9096x; 1.3171x over previous
#include <cuda_runtime.h>
#include <math.h>

// Problem constants
#define B_ 4
#define CIN_ 128
#define COUT_ 128
#define H_ 128
#define W_ 128
#define HW_ (H_*W_)
#define KK_ 9
#define CK_ (KK_*CIN_)   // 1152

// Scratch (device globals; no allocation allowed)
__device__ float g_nhwc[B_*HW_*CIN_];          // inp transposed to NHWC
__device__ float g_wt[CK_*COUT_];              // w_dc reordered: [ck][oc], ck=k*128+c
__device__ float g_py[B_*KK_*HW_];             // absolute sample y
__device__ float g_px[B_*KK_*HW_];             // absolute sample x
__device__ float g_m [B_*KK_*HW_];             // sigmoid mask

// ---------------------------------------------------------------------------
// Kernel 1: NCHW -> NHWC transpose of inp (per b: [C][HW] -> [HW][C])
// ---------------------------------------------------------------------------
__global__ void k_transpose(const float* __restrict__ inp) {
    __shared__ float tile[32][33];
    int b  = blockIdx.z;
    int c0 = blockIdx.y * 32;
    int h0 = blockIdx.x * 32;
    int tx = threadIdx.x, ty = threadIdx.y;
    #pragma unroll
    for (int i = 0; i < 4; ++i) {
        int c = c0 + ty + 8*i;
        tile[ty + 8*i][tx] = inp[(b*CIN_ + c)*HW_ + h0 + tx];
    }
    __syncthreads();
    #pragma unroll
    for (int i = 0; i < 4; ++i) {
        int hw = h0 + ty + 8*i;
        g_nhwc[(b*HW_ + hw)*CIN_ + c0 + tx] = tile[tx][ty + 8*i];
    }
}

// ---------------------------------------------------------------------------
// Kernel 2: reorder w_dc[oc][c][k] -> g_wt[(k*128+c)][oc]  (oc contiguous)
// ---------------------------------------------------------------------------
__global__ void k_wprep(const float* __restrict__ w_dc) {
    int t = blockIdx.x * blockDim.x + threadIdx.x;
    if (t >= COUT_*CK_) return;
    int oc = t / CK_;
    int r  = t % CK_;
    int c  = r / KK_;
    int k  = r % KK_;
    int ck = k*CIN_ + c;
    g_wt[ck*COUT_ + oc] = w_dc[t];
}

// ---------------------------------------------------------------------------
// Kernel 3: offset conv (27 channels) + positions/masks
// ---------------------------------------------------------------------------
__global__ void __launch_bounds__(256) k_offconv(const float* __restrict__ feat,
                                                 const float* __restrict__ w_off,
                                                 const float* __restrict__ b_off) {
    __shared__ float ws[32*9*28];
    int tid = threadIdx.x;
    int b = blockIdx.x >> 6;
    int y = ((blockIdx.x & 63) << 1) + (tid >> 7);
    int x = tid & 127;

    float acc[28];
    #pragma unroll
    for (int i = 0; i < 28; ++i) acc[i] = 0.f;

    for (int cc = 0; cc < 4; ++cc) {
        __syncthreads();
        for (int e = tid; e < 32*9*27; e += 256) {
            int oc = e % 27;
            int t2 = e / 27;
            int k  = t2 % 9;
            int cl = t2 / 9;
            ws[(cl*9+k)*28 + oc] = w_off[(oc*CIN_ + (cc*32 + cl))*KK_ + k];
        }
        for (int e = tid; e < 32*9; e += 256) ws[e*28 + 27] = 0.f;
        __syncthreads();

        for (int cl = 0; cl < 32; ++cl) {
            int c = cc*32 + cl;
            const float* fb = feat + (b*CIN_ + c)*HW_;
            float f[9];
            #pragma unroll
            for (int r = 0; r < 3; ++r) {
                #pragma unroll
                for (int s = 0; s < 3; ++s) {
                    int yy = y - 1 + r, xx = x - 1 + s;
                    bool v = (yy >= 0) && (yy < H_) && (xx >= 0) && (xx < W_);
                    f[r*3+s] = v ? fb[yy*W_ + xx] : 0.f;
                }
            }
            #pragma unroll
            for (int k = 0; k < 9; ++k) {
                float v = f[k];
                const float4* w4p = (const float4*)(ws + (cl*9+k)*28);
                #pragma unroll
                for (int q = 0; q < 7; ++q) {
                    float4 w4 = w4p[q];
                    acc[q*4+0] = fmaf(v, w4.x, acc[q*4+0]);
                    acc[q*4+1] = fmaf(v, w4.y, acc[q*4+1]);
                    acc[q*4+2] = fmaf(v, w4.z, acc[q*4+2]);
                    acc[q*4+3] = fmaf(v, w4.w, acc[q*4+3]);
                }
            }
        }
    }
    #pragma unroll
    for (int oc = 0; oc < 27; ++oc) acc[oc] += b_off[oc];

    #pragma unroll
    for (int k = 0; k < 9; ++k) {
        float py = acc[2*k]     + (float)(y + (k/3) - 1);
        float px = acc[2*k + 1] + (float)(x + (k%3) - 1);
        float m  = 1.f / (1.f + expf(-acc[18 + k]));
        int idx = (b*KK_ + k)*HW_ + y*W_ + x;
        g_py[idx] = py;
        g_px[idx] = px;
        g_m[idx]  = m;
    }
}

// ---------------------------------------------------------------------------
// Kernel 4: main deformable conv, v3.
// Gather lanes span CHANNELS (coalesced LDG: 4 lines/warp-load instead of 32).
// val_s uses XOR swizzle (p ^= (ck>>2 & 15)<<2) to keep transposed scalar
// stores at 2-way conflict while preserving float4 GEMM reads.
// ---------------------------------------------------------------------------
#define PX_ 64
#define CKC_ 64          // ck per chunk
#define NCHUNK_ 18

__global__ void __launch_bounds__(256, 3) k_dcn(const float* __restrict__ b_dc,
                                                float* __restrict__ out) {
    extern __shared__ float smem[];
    float* val_s = smem;                         // [64][64] swizzled, 16KB
    float* w_s   = smem + CKC_*PX_;              // [64][128]  32KB
    int*   cb_s  = (int*)  (w_s + CKC_*COUT_);   // [9*64][4]  9.2KB
    float* cw_s  = (float*)(cb_s + 9*PX_*4);     // [9*64][4]  9.2KB

    int tid = threadIdx.x;
    int blk = blockIdx.x;
    int b  = blk >> 8;
    int y  = (blk >> 1) & 127;
    int x0 = (blk & 1) << 6;

    // ---- Phase 1: corner bases + combined weights for 9 taps x 64 px ----
    for (int kp = tid; kp < 9*PX_; kp += 256) {
        int k = kp >> 6, p = kp & 63;
        int x = x0 + p;
        int idx = (b*KK_ + k)*HW_ + y*W_ + x;
        float py = g_py[idx], px = g_px[idx], m = g_m[idx];
        float y0f = floorf(py), x0f = floorf(px);
        float ly = py - y0f, lx = px - x0f;
        y0f = fminf(fmaxf(y0f, -4.f), 132.f);
        x0f = fminf(fmaxf(x0f, -4.f), 132.f);
        int yi = (int)y0f, xi = (int)x0f;
        float wgt[4] = {(1.f-ly)*(1.f-lx), (1.f-ly)*lx, ly*(1.f-lx), ly*lx};
        const int dy[4] = {0,0,1,1};
        const int dx[4] = {0,1,0,1};
        #pragma unroll
        for (int j = 0; j < 4; ++j) {
            int yy = yi + dy[j], xx = xi + dx[j];
            bool v = (yy >= 0) && (yy < H_) && (xx >= 0) && (xx < W_);
            int yc = min(max(yy, 0), H_-1);
            int xc = min(max(xx, 0), W_-1);
            cb_s[kp*4 + j] = ((b*H_ + yc)*W_ + xc) * CIN_;
            cw_s[kp*4 + j] = v ? wgt[j]*m : 0.f;
        }
    }

    // GEMM thread tile: 8 oc x 4 px
    int pq  = tid & 15;           // px-quad index (px0 = pq*4)
    int oc0 = (tid >> 4) << 3;
    float acc[8][4];
    #pragma unroll
    for (int j = 0; j < 8; ++j)
        #pragma unroll
        for (int q = 0; q < 4; ++q) acc[j][q] = 0.f;

    // gather lane mapping (fixed per thread)
    int wid  = tid >> 5;
    int lane = tid & 31;
    int quad = lane & 15;         // channel quad 0..15 (64 ch per chunk)
    int pl   = lane >> 4;         // pixel parity within pair
    int psw  = (quad << 2);       // swizzle for rows quad*4..quad*4+3

    // ---- Main loop over 18 K-chunks ----
    for (int chunk = 0; chunk < NCHUNK_; ++chunk) {
        int k  = chunk >> 1;
        int c0 = (chunk & 1) << 6;
        __syncthreads();

        // stage weights: w_s[ckl][oc] <- g_wt[chunk*64 + ckl][oc], 32KB
        {
            const float4* src = (const float4*)(g_wt + chunk*CKC_*COUT_);
            float4* dst = (float4*)w_s;
            #pragma unroll
            for (int i = 0; i < 8; ++i) dst[tid + (i << 8)] = src[tid + (i << 8)];
        }

        // gather: warp-iter covers 2 pixels x 64 channels; lanes span channels
        #pragma unroll
        for (int it = 0; it < 4; ++it) {
            int p = ((wid << 2) + it) * 2 + pl;      // pixel 0..63
            const int*   cb = cb_s + ((k << 6) + p)*4;
            const float* cw = cw_s + ((k << 6) + p)*4;
            float a0 = 0.f, a1 = 0.f, a2 = 0.f, a3 = 0.f;
            #pragma unroll
            for (int j = 0; j < 4; ++j) {
                float w = cw[j];
                float4 t = *(const float4*)(g_nhwc + cb[j] + c0 + (quad << 2));
                a0 = fmaf(w, t.x, a0);
                a1 = fmaf(w, t.y, a1);
                a2 = fmaf(w, t.z, a2);
                a3 = fmaf(w, t.w, a3);
            }
            int ckl = quad << 2;
            int ps  = p ^ psw;                        // swizzled pixel slot
            val_s[(ckl+0)*PX_ + ps] = a0;
            val_s[(ckl+1)*PX_ + ps] = a1;
            val_s[(ckl+2)*PX_ + ps] = a2;
            val_s[(ckl+3)*PX_ + ps] = a3;
        }
        __syncthreads();

        // GEMM accumulate over this chunk's 64 ck (swizzled v read)
        const float4* v4 = (const float4*)val_s;
        #pragma unroll 8
        for (int ckl = 0; ckl < CKC_; ++ckl) {
            float4 v  = v4[ckl*16 + (pq ^ ((ckl >> 2) & 15))];
            float4 wa = *(const float4*)(w_s + ckl*COUT_ + oc0);
            float4 wb = *(const float4*)(w_s + ckl*COUT_ + oc0 + 4);
            float wv[8] = {wa.x, wa.y, wa.z, wa.w, wb.x, wb.y, wb.z, wb.w};
            #pragma unroll
            for (int j = 0; j < 8; ++j) {
                acc[j][0] = fmaf(wv[j], v.x, acc[j][0]);
                acc[j][1] = fmaf(wv[j], v.y, acc[j][1]);
                acc[j][2] = fmaf(wv[j], v.z, acc[j][2]);
                acc[j][3] = fmaf(wv[j], v.w, acc[j][3]);
            }
        }
    }

    // ---- Epilogue: NCHW output, float4 per oc ----
    int px0 = pq << 2;
    #pragma unroll
    for (int j = 0; j < 8; ++j) {
        int oc = oc0 + j;
        float bv = b_dc[oc];
        float4 o4 = make_float4(acc[j][0]+bv, acc[j][1]+bv, acc[j][2]+bv, acc[j][3]+bv);
        *(float4*)(out + ((b*COUT_ + oc)*H_ + y)*W_ + x0 + px0) = o4;
    }
}

// ---------------------------------------------------------------------------
extern "C" void kernel_launch(void* const* d_in, const int* in_sizes, int n_in,
                              void* d_out, int out_size) {
    const float* inp   = (const float*)d_in[0];
    const float* feat  = (const float*)d_in[1];
    const float* w_off = (const float*)d_in[2];
    const float* b_off = (const float*)d_in[3];
    const float* w_dc  = (const float*)d_in[4];
    const float* b_dc  = (const float*)d_in[5];
    float* out = (float*)d_out;

    const int dyn_smem = (CKC_*PX_ + CKC_*COUT_ + 9*PX_*4*2) * 4;  // 67584 B
    cudaFuncSetAttribute(k_dcn, cudaFuncAttributeMaxDynamicSharedMemorySize, dyn_smem);

    k_transpose<<<dim3(HW_/32, CIN_/32, B_), dim3(32, 8)>>>(inp);
    k_wprep<<<(COUT_*CK_ + 255)/256, 256>>>(w_dc);
    k_offconv<<<B_*(H_/2), 256>>>(feat, w_off, b_off);
    k_dcn<<<B_*H_*(W_/64), 256, dyn_smem>>>(b_dc, out);
}

// round 14
// speedup vs baseline: 2.2867x; 1.1975x over previous
#include <cuda_runtime.h>
#include <cuda_bf16.h>
#include <mma.h>
#include <math.h>
#include <stdint.h>

using namespace nvcuda;

// Problem constants
#define B_ 4
#define CIN_ 128
#define COUT_ 128
#define H_ 128
#define W_ 128
#define HW_ (H_*W_)
#define KK_ 9
#define CK_ (KK_*CIN_)   // 1152

// Scratch (device globals; no allocation allowed)
__device__ float g_nhwc[B_*HW_*CIN_];            // inp transposed to NHWC
__device__ __nv_bfloat16 g_wbh[CK_*COUT_];       // weight hi  [ck][oc]
__device__ __nv_bfloat16 g_wbl[CK_*COUT_];       // weight lo  [ck][oc]
__device__ float g_py[B_*KK_*HW_];               // absolute sample y
__device__ float g_px[B_*KK_*HW_];               // absolute sample x
__device__ float g_m [B_*KK_*HW_];               // sigmoid mask

// ---------------------------------------------------------------------------
// Kernel 1: NCHW -> NHWC transpose of inp
// ---------------------------------------------------------------------------
__global__ void k_transpose(const float* __restrict__ inp) {
    __shared__ float tile[32][33];
    int b  = blockIdx.z;
    int c0 = blockIdx.y * 32;
    int h0 = blockIdx.x * 32;
    int tx = threadIdx.x, ty = threadIdx.y;
    #pragma unroll
    for (int i = 0; i < 4; ++i) {
        int c = c0 + ty + 8*i;
        tile[ty + 8*i][tx] = inp[(b*CIN_ + c)*HW_ + h0 + tx];
    }
    __syncthreads();
    #pragma unroll
    for (int i = 0; i < 4; ++i) {
        int hw = h0 + ty + 8*i;
        g_nhwc[(b*HW_ + hw)*CIN_ + c0 + tx] = tile[tx][ty + 8*i];
    }
}

// ---------------------------------------------------------------------------
// Kernel 2: weight prep — bf16 hi/lo split, layout [ck][oc], ck = k*128+c
// ---------------------------------------------------------------------------
__global__ void k_wprep(const float* __restrict__ w_dc) {
    int t = blockIdx.x * blockDim.x + threadIdx.x;
    if (t >= COUT_*CK_) return;
    int ck = t >> 7;          // 0..1151
    int oc = t & 127;
    int k  = ck >> 7;
    int c  = ck & 127;
    float w = w_dc[(oc*CIN_ + c)*KK_ + k];
    __nv_bfloat16 hi = __float2bfloat16(w);
    __nv_bfloat16 lo = __float2bfloat16(w - __bfloat162float(hi));
    g_wbh[ck*COUT_ + oc] = hi;
    g_wbl[ck*COUT_ + oc] = lo;
}

// ---------------------------------------------------------------------------
// Kernel 3: offset conv (27 channels) + positions/masks (unchanged)
// ---------------------------------------------------------------------------
__global__ void __launch_bounds__(256) k_offconv(const float* __restrict__ feat,
                                                 const float* __restrict__ w_off,
                                                 const float* __restrict__ b_off) {
    __shared__ float ws[32*9*28];
    int tid = threadIdx.x;
    int b = blockIdx.x >> 6;
    int y = ((blockIdx.x & 63) << 1) + (tid >> 7);
    int x = tid & 127;

    float acc[28];
    #pragma unroll
    for (int i = 0; i < 28; ++i) acc[i] = 0.f;

    for (int cc = 0; cc < 4; ++cc) {
        __syncthreads();
        for (int e = tid; e < 32*9*27; e += 256) {
            int oc = e % 27;
            int t2 = e / 27;
            int k  = t2 % 9;
            int cl = t2 / 9;
            ws[(cl*9+k)*28 + oc] = w_off[(oc*CIN_ + (cc*32 + cl))*KK_ + k];
        }
        for (int e = tid; e < 32*9; e += 256) ws[e*28 + 27] = 0.f;
        __syncthreads();

        for (int cl = 0; cl < 32; ++cl) {
            int c = cc*32 + cl;
            const float* fb = feat + (b*CIN_ + c)*HW_;
            float f[9];
            #pragma unroll
            for (int r = 0; r < 3; ++r) {
                #pragma unroll
                for (int s = 0; s < 3; ++s) {
                    int yy = y - 1 + r, xx = x - 1 + s;
                    bool v = (yy >= 0) && (yy < H_) && (xx >= 0) && (xx < W_);
                    f[r*3+s] = v ? fb[yy*W_ + xx] : 0.f;
                }
            }
            #pragma unroll
            for (int k = 0; k < 9; ++k) {
                float v = f[k];
                const float4* w4p = (const float4*)(ws + (cl*9+k)*28);
                #pragma unroll
                for (int q = 0; q < 7; ++q) {
                    float4 w4 = w4p[q];
                    acc[q*4+0] = fmaf(v, w4.x, acc[q*4+0]);
                    acc[q*4+1] = fmaf(v, w4.y, acc[q*4+1]);
                    acc[q*4+2] = fmaf(v, w4.z, acc[q*4+2]);
                    acc[q*4+3] = fmaf(v, w4.w, acc[q*4+3]);
                }
            }
        }
    }
    #pragma unroll
    for (int oc = 0; oc < 27; ++oc) acc[oc] += b_off[oc];

    #pragma unroll
    for (int k = 0; k < 9; ++k) {
        float py = acc[2*k]     + (float)(y + (k/3) - 1);
        float px = acc[2*k + 1] + (float)(x + (k%3) - 1);
        float m  = 1.f / (1.f + expf(-acc[18 + k]));
        int idx = (b*KK_ + k)*HW_ + y*W_ + x;
        g_py[idx] = py;
        g_px[idx] = px;
        g_m[idx]  = m;
    }
}

// ---------------------------------------------------------------------------
// Kernel 4: main deformable conv, v5 — WMMA bf16 2-term split (legacy HMMA).
// Block = 64 px x 128 oc, 8 warps, warp tile 16px x 64oc.
// 18 K-chunks of 64 ck: gather+convert A hi/lo [64px][64ck] (ld=72),
// stage W hi/lo [64ck][128oc] (ld=136), 4 ktiles x 4 ntiles x 3 split-mmas.
// ---------------------------------------------------------------------------
#define PX_ 64
#define CKC_ 64
#define NCHUNK_ 18
#define A_LD 72           // elements (144B rows, bank-rotating)
#define B_LD 136          // elements (272B rows, bank-rotating)
#define C_LD 132          // floats

// smem byte offsets
#define OFF_AH 0
#define OFF_AL (OFF_AH + PX_*A_LD*2)          //  9216
#define OFF_BH (OFF_AL + PX_*A_LD*2)          // 18432
#define OFF_BL (OFF_BH + CKC_*B_LD*2)         // 35840
#define OFF_CB (OFF_BL + CKC_*B_LD*2)         // 53248  int [9*64][4]
#define OFF_CW (OFF_CB + 9*PX_*4*4)           // 62464  float [9*64][4]
#define SMEM_DCN (OFF_CW + 9*PX_*4*4)         // 71680

__global__ void __launch_bounds__(256, 2) k_dcn(const float* __restrict__ b_dc,
                                                float* __restrict__ out) {
    extern __shared__ char smem[];
    __nv_bfloat16* a_hi = (__nv_bfloat16*)(smem + OFF_AH);
    __nv_bfloat16* a_lo = (__nv_bfloat16*)(smem + OFF_AL);
    __nv_bfloat16* b_hi = (__nv_bfloat16*)(smem + OFF_BH);
    __nv_bfloat16* b_lo = (__nv_bfloat16*)(smem + OFF_BL);
    int*   cb_s = (int*)  (smem + OFF_CB);
    float* cw_s = (float*)(smem + OFF_CW);
    float* c_s  = (float*)smem;                 // epilogue alias over A/B

    int tid  = threadIdx.x;
    int wid  = tid >> 5;
    int lane = tid & 31;
    int blk  = blockIdx.x;
    int b  = blk >> 8;
    int y  = (blk >> 1) & 127;
    int x0 = (blk & 1) << 6;

    // ---- Phase 1: corner bases + combined weights for 9 taps x 64 px ----
    for (int kp = tid; kp < 9*PX_; kp += 256) {
        int k = kp >> 6, p = kp & 63;
        int x = x0 + p;
        int idx = (b*KK_ + k)*HW_ + y*W_ + x;
        float py = g_py[idx], px = g_px[idx], m = g_m[idx];
        float y0f = floorf(py), x0f = floorf(px);
        float ly = py - y0f, lx = px - x0f;
        y0f = fminf(fmaxf(y0f, -4.f), 132.f);
        x0f = fminf(fmaxf(x0f, -4.f), 132.f);
        int yi = (int)y0f, xi = (int)x0f;
        float wgt[4] = {(1.f-ly)*(1.f-lx), (1.f-ly)*lx, ly*(1.f-lx), ly*lx};
        const int dy[4] = {0,0,1,1};
        const int dx[4] = {0,1,0,1};
        #pragma unroll
        for (int j = 0; j < 4; ++j) {
            int yy = yi + dy[j], xx = xi + dx[j];
            bool v = (yy >= 0) && (yy < H_) && (xx >= 0) && (xx < W_);
            int yc = min(max(yy, 0), H_-1);
            int xc = min(max(xx, 0), W_-1);
            cb_s[kp*4 + j] = ((b*H_ + yc)*W_ + xc) * CIN_;
            cw_s[kp*4 + j] = v ? wgt[j]*m : 0.f;
        }
    }

    // warp tile: mtile = wid>>1 (16 px), ntile0 = (wid&1)*4 (4 x 16 oc)
    int mtile  = wid >> 1;
    int ntile0 = (wid & 1) << 2;

    wmma::fragment<wmma::accumulator, 16, 16, 16, float> accf[4];
    #pragma unroll
    for (int nt = 0; nt < 4; ++nt) wmma::fill_fragment(accf[nt], 0.f);

    // gather lane mapping
    int quad = lane & 15;        // channel quad 0..15 (64 ch/chunk)
    int pl   = lane >> 4;        // pixel parity

    for (int chunk = 0; chunk < NCHUNK_; ++chunk) {
        int k  = chunk >> 1;
        int c0 = (chunk & 1) << 6;
        __syncthreads();   // prior chunk's MMA reads done before overwrite

        // stage weight tiles hi/lo: row ckl -> 256B contiguous (16 uint4)
        {
            const uint4* srcH = (const uint4*)(g_wbh + chunk*CKC_*COUT_);
            const uint4* srcL = (const uint4*)(g_wbl + chunk*CKC_*COUT_);
            #pragma unroll
            for (int i = 0; i < 4; ++i) {
                int idx = tid + (i << 8);       // 0..1023
                int row = idx >> 4, col = idx & 15;
                *(uint4*)((char*)b_hi + row*(B_LD*2) + col*16) = srcH[idx];
                *(uint4*)((char*)b_lo + row*(B_LD*2) + col*16) = srcL[idx];
            }
        }

        // gather + convert into A hi/lo [px][ck], ld=72
        #pragma unroll
        for (int it = 0; it < 4; ++it) {
            int p = ((wid << 2) + it) * 2 + pl;      // 0..63
            const int*   cb = cb_s + ((k << 6) + p)*4;
            const float* cw = cw_s + ((k << 6) + p)*4;
            float a0 = 0.f, a1 = 0.f, a2 = 0.f, a3 = 0.f;
            #pragma unroll
            for (int j = 0; j < 4; ++j) {
                float w = cw[j];
                float4 t = *(const float4*)(g_nhwc + cb[j] + c0 + (quad << 2));
                a0 = fmaf(w, t.x, a0);
                a1 = fmaf(w, t.y, a1);
                a2 = fmaf(w, t.z, a2);
                a3 = fmaf(w, t.w, a3);
            }
            __nv_bfloat16 h0 = __float2bfloat16(a0);
            __nv_bfloat16 h1 = __float2bfloat16(a1);
            __nv_bfloat16 h2 = __float2bfloat16(a2);
            __nv_bfloat16 h3 = __float2bfloat16(a3);
            __nv_bfloat16 l0 = __float2bfloat16(a0 - __bfloat162float(h0));
            __nv_bfloat16 l1 = __float2bfloat16(a1 - __bfloat162float(h1));
            __nv_bfloat16 l2 = __float2bfloat16(a2 - __bfloat162float(h2));
            __nv_bfloat16 l3 = __float2bfloat16(a3 - __bfloat162float(h3));
            uint32_t hp0, hp1, lp0, lp1;
            {
                __nv_bfloat162 t0(h0, h1), t1(h2, h3), t2(l0, l1), t3(l2, l3);
                hp0 = *(uint32_t*)&t0; hp1 = *(uint32_t*)&t1;
                lp0 = *(uint32_t*)&t2; lp1 = *(uint32_t*)&t3;
            }
            uint32_t off = (uint32_t)(p*(A_LD*2) + quad*8);
            *(uint2*)((char*)a_hi + off) = make_uint2(hp0, hp1);
            *(uint2*)((char*)a_lo + off) = make_uint2(lp0, lp1);
        }
        __syncthreads();

        // WMMA: 4 k-tiles x (4 n-tiles x 3 split products)
        #pragma unroll
        for (int kt = 0; kt < 4; ++kt) {
            wmma::fragment<wmma::matrix_a, 16, 16, 16, __nv_bfloat16, wmma::row_major> fah, fal;
            wmma::load_matrix_sync(fah, a_hi + mtile*16*A_LD + kt*16, A_LD);
            wmma::load_matrix_sync(fal, a_lo + mtile*16*A_LD + kt*16, A_LD);
            #pragma unroll
            for (int nt = 0; nt < 4; ++nt) {
                wmma::fragment<wmma::matrix_b, 16, 16, 16, __nv_bfloat16, wmma::row_major> fbh, fbl;
                int ncol = (ntile0 + nt) * 16;
                wmma::load_matrix_sync(fbh, b_hi + kt*16*B_LD + ncol, B_LD);
                wmma::load_matrix_sync(fbl, b_lo + kt*16*B_LD + ncol, B_LD);
                wmma::mma_sync(accf[nt], fah, fbh, accf[nt]);
                wmma::mma_sync(accf[nt], fah, fbl, accf[nt]);
                wmma::mma_sync(accf[nt], fal, fbh, accf[nt]);
            }
        }
    }

    // ---- Epilogue: C frags -> smem (alias), bias, NCHW stores ----
    __syncthreads();
    #pragma unroll
    for (int nt = 0; nt < 4; ++nt)
        wmma::store_matrix_sync(c_s + mtile*16*C_LD + (ntile0 + nt)*16,
                                accf[nt], C_LD, wmma::mem_row_major);
    __syncthreads();

    {
        int oc = tid >> 1;
        int ph = (tid & 1) << 5;            // px half: 0 or 32
        float bv = __ldg(b_dc + oc);
        float* ob = out + ((b*COUT_ + oc)*H_ + y)*W_ + x0;
        #pragma unroll
        for (int j = 0; j < 8; ++j) {
            int px = ph + (j << 2);
            float4 v;
            v.x = c_s[(px+0)*C_LD + oc] + bv;
            v.y = c_s[(px+1)*C_LD + oc] + bv;
            v.z = c_s[(px+2)*C_LD + oc] + bv;
            v.w = c_s[(px+3)*C_LD + oc] + bv;
            *(float4*)(ob + px) = v;
        }
    }
}

// ---------------------------------------------------------------------------
extern "C" void kernel_launch(void* const* d_in, const int* in_sizes, int n_in,
                              void* d_out, int out_size) {
    const float* inp   = (const float*)d_in[0];
    const float* feat  = (const float*)d_in[1];
    const float* w_off = (const float*)d_in[2];
    const float* b_off = (const float*)d_in[3];
    const float* w_dc  = (const float*)d_in[4];
    const float* b_dc  = (const float*)d_in[5];
    float* out = (float*)d_out;

    cudaFuncSetAttribute(k_dcn, cudaFuncAttributeMaxDynamicSharedMemorySize, SMEM_DCN);

    k_transpose<<<dim3(HW_/32, CIN_/32, B_), dim3(32, 8)>>>(inp);
    k_wprep<<<(COUT_*CK_ + 255)/256, 256>>>(w_dc);
    k_offconv<<<B_*(H_/2), 256>>>(feat, w_off, b_off);
    k_dcn<<<B_*H_*(W_/64), 256, SMEM_DCN>>>(b_dc, out);
}

// round 17
// speedup vs baseline: 2.5150x; 1.0998x over previous
#include <cuda_runtime.h>
#include <cuda_bf16.h>
#include <mma.h>
#include <math.h>
#include <stdint.h>

using namespace nvcuda;

// Problem constants
#define B_ 4
#define CIN_ 128
#define COUT_ 128
#define H_ 128
#define W_ 128
#define HW_ (H_*W_)
#define KK_ 9
#define CK_ (KK_*CIN_)   // 1152

// Scratch (device globals; no allocation allowed)
__device__ float g_nhwc[B_*HW_*CIN_];            // inp transposed to NHWC
__device__ __nv_bfloat16 g_wbh[CK_*COUT_];       // weight hi  [ck][oc]
__device__ __nv_bfloat16 g_wbl[CK_*COUT_];       // weight lo  [ck][oc]
__device__ float g_py[B_*KK_*HW_];               // absolute sample y
__device__ float g_px[B_*KK_*HW_];               // absolute sample x
__device__ float g_m [B_*KK_*HW_];               // sigmoid mask

// ---------------------------------------------------------------------------
// Kernel 1: NCHW -> NHWC transpose of inp
// ---------------------------------------------------------------------------
__global__ void k_transpose(const float* __restrict__ inp) {
    __shared__ float tile[32][33];
    int b  = blockIdx.z;
    int c0 = blockIdx.y * 32;
    int h0 = blockIdx.x * 32;
    int tx = threadIdx.x, ty = threadIdx.y;
    #pragma unroll
    for (int i = 0; i < 4; ++i) {
        int c = c0 + ty + 8*i;
        tile[ty + 8*i][tx] = inp[(b*CIN_ + c)*HW_ + h0 + tx];
    }
    __syncthreads();
    #pragma unroll
    for (int i = 0; i < 4; ++i) {
        int hw = h0 + ty + 8*i;
        g_nhwc[(b*HW_ + hw)*CIN_ + c0 + tx] = tile[tx][ty + 8*i];
    }
}

// ---------------------------------------------------------------------------
// Kernel 2: weight prep — bf16 hi/lo split, layout [ck][oc], ck = k*128+c
// ---------------------------------------------------------------------------
__global__ void k_wprep(const float* __restrict__ w_dc) {
    int t = blockIdx.x * blockDim.x + threadIdx.x;
    if (t >= COUT_*CK_) return;
    int ck = t >> 7;          // 0..1151
    int oc = t & 127;
    int k  = ck >> 7;
    int c  = ck & 127;
    float w = w_dc[(oc*CIN_ + c)*KK_ + k];
    __nv_bfloat16 hi = __float2bfloat16(w);
    __nv_bfloat16 lo = __float2bfloat16(w - __bfloat162float(hi));
    g_wbh[ck*COUT_ + oc] = hi;
    g_wbl[ck*COUT_ + oc] = lo;
}

// ---------------------------------------------------------------------------
// Kernel 3: offset conv (27 channels) + positions/masks (unchanged)
// ---------------------------------------------------------------------------
__global__ void __launch_bounds__(256) k_offconv(const float* __restrict__ feat,
                                                 const float* __restrict__ w_off,
                                                 const float* __restrict__ b_off) {
    __shared__ float ws[32*9*28];
    int tid = threadIdx.x;
    int b = blockIdx.x >> 6;
    int y = ((blockIdx.x & 63) << 1) + (tid >> 7);
    int x = tid & 127;

    float acc[28];
    #pragma unroll
    for (int i = 0; i < 28; ++i) acc[i] = 0.f;

    for (int cc = 0; cc < 4; ++cc) {
        __syncthreads();
        for (int e = tid; e < 32*9*27; e += 256) {
            int oc = e % 27;
            int t2 = e / 27;
            int k  = t2 % 9;
            int cl = t2 / 9;
            ws[(cl*9+k)*28 + oc] = w_off[(oc*CIN_ + (cc*32 + cl))*KK_ + k];
        }
        for (int e = tid; e < 32*9; e += 256) ws[e*28 + 27] = 0.f;
        __syncthreads();

        for (int cl = 0; cl < 32; ++cl) {
            int c = cc*32 + cl;
            const float* fb = feat + (b*CIN_ + c)*HW_;
            float f[9];
            #pragma unroll
            for (int r = 0; r < 3; ++r) {
                #pragma unroll
                for (int s = 0; s < 3; ++s) {
                    int yy = y - 1 + r, xx = x - 1 + s;
                    bool v = (yy >= 0) && (yy < H_) && (xx >= 0) && (xx < W_);
                    f[r*3+s] = v ? fb[yy*W_ + xx] : 0.f;
                }
            }
            #pragma unroll
            for (int k = 0; k < 9; ++k) {
                float v = f[k];
                const float4* w4p = (const float4*)(ws + (cl*9+k)*28);
                #pragma unroll
                for (int q = 0; q < 7; ++q) {
                    float4 w4 = w4p[q];
                    acc[q*4+0] = fmaf(v, w4.x, acc[q*4+0]);
                    acc[q*4+1] = fmaf(v, w4.y, acc[q*4+1]);
                    acc[q*4+2] = fmaf(v, w4.z, acc[q*4+2]);
                    acc[q*4+3] = fmaf(v, w4.w, acc[q*4+3]);
                }
            }
        }
    }
    #pragma unroll
    for (int oc = 0; oc < 27; ++oc) acc[oc] += b_off[oc];

    #pragma unroll
    for (int k = 0; k < 9; ++k) {
        float py = acc[2*k]     + (float)(y + (k/3) - 1);
        float px = acc[2*k + 1] + (float)(x + (k%3) - 1);
        float m  = 1.f / (1.f + expf(-acc[18 + k]));
        int idx = (b*KK_ + k)*HW_ + y*W_ + x;
        g_py[idx] = py;
        g_px[idx] = px;
        g_m[idx]  = m;
    }
}

// ---------------------------------------------------------------------------
// Kernel 4: main deformable conv, v6 — WMMA bf16 3-term split, full-row block.
// Block = 128 px x 128 oc, 8 warps, warp tile 32px x 64oc (2m x 4n frags).
// 18 K-chunks of 64 ck: gather+convert A hi/lo [128px][64ck] (ld=72),
// stage W hi/lo [64ck][128oc] (ld=136). A-frags held across n-loop.
// ---------------------------------------------------------------------------
#define PX_ 128
#define CKC_ 64
#define NCHUNK_ 18
#define A_LD 72           // elements (144B rows, bank-rotating)
#define B_LD 136          // elements (272B rows, bank-rotating)
#define C_LD 132          // floats

// smem byte offsets
#define OFF_AH 0
#define OFF_AL (OFF_AH + PX_*A_LD*2)          // 18432
#define OFF_BH (OFF_AL + PX_*A_LD*2)          // 36864
#define OFF_BL (OFF_BH + CKC_*B_LD*2)         // 54272
#define OFF_CB (OFF_BL + CKC_*B_LD*2)         // 71680  int  [9*128][4]
#define OFF_CW (OFF_CB + 9*PX_*4*4)           // 90112  float[9*128][4]
#define SMEM_DCN (OFF_CW + 9*PX_*4*4)         // 108544

__global__ void __launch_bounds__(256, 2) k_dcn(const float* __restrict__ b_dc,
                                                float* __restrict__ out) {
    extern __shared__ char smem[];
    __nv_bfloat16* a_hi = (__nv_bfloat16*)(smem + OFF_AH);
    __nv_bfloat16* a_lo = (__nv_bfloat16*)(smem + OFF_AL);
    __nv_bfloat16* b_hi = (__nv_bfloat16*)(smem + OFF_BH);
    __nv_bfloat16* b_lo = (__nv_bfloat16*)(smem + OFF_BL);
    int*   cb_s = (int*)  (smem + OFF_CB);
    float* cw_s = (float*)(smem + OFF_CW);
    float* c_s  = (float*)smem;                 // epilogue alias over A/B

    int tid  = threadIdx.x;
    int wid  = tid >> 5;
    int lane = tid & 31;
    int blk  = blockIdx.x;
    int b = blk >> 7;
    int y = blk & 127;

    // ---- Phase 1: corner bases + combined weights for 9 taps x 128 px ----
    for (int kp = tid; kp < 9*PX_; kp += 256) {
        int k = kp >> 7, p = kp & 127;
        int idx = (b*KK_ + k)*HW_ + y*W_ + p;
        float py = g_py[idx], px = g_px[idx], m = g_m[idx];
        float y0f = floorf(py), x0f = floorf(px);
        float ly = py - y0f, lx = px - x0f;
        y0f = fminf(fmaxf(y0f, -4.f), 132.f);
        x0f = fminf(fmaxf(x0f, -4.f), 132.f);
        int yi = (int)y0f, xi = (int)x0f;
        float wgt[4] = {(1.f-ly)*(1.f-lx), (1.f-ly)*lx, ly*(1.f-lx), ly*lx};
        const int dy[4] = {0,0,1,1};
        const int dx[4] = {0,1,0,1};
        #pragma unroll
        for (int j = 0; j < 4; ++j) {
            int yy = yi + dy[j], xx = xi + dx[j];
            bool v = (yy >= 0) && (yy < H_) && (xx >= 0) && (xx < W_);
            int yc = min(max(yy, 0), H_-1);
            int xc = min(max(xx, 0), W_-1);
            cb_s[kp*4 + j] = ((b*H_ + yc)*W_ + xc) * CIN_;
            cw_s[kp*4 + j] = v ? wgt[j]*m : 0.f;
        }
    }

    // warp tile: mtile2 = wid>>1 (32 px), ntile0 = (wid&1)*4 (4 x 16 oc)
    int mtile2 = wid >> 1;
    int ntile0 = (wid & 1) << 2;

    wmma::fragment<wmma::accumulator, 16, 16, 16, float> accf[2][4];
    #pragma unroll
    for (int m = 0; m < 2; ++m)
        #pragma unroll
        for (int nt = 0; nt < 4; ++nt) wmma::fill_fragment(accf[m][nt], 0.f);

    // gather lane mapping
    int quad = lane & 15;        // channel quad 0..15 (64 ch/chunk)
    int pl   = lane >> 4;        // pixel parity

    for (int chunk = 0; chunk < NCHUNK_; ++chunk) {
        int k  = chunk >> 1;
        int c0 = (chunk & 1) << 6;
        __syncthreads();   // prior chunk's MMA reads done before overwrite

        // stage weight tiles hi/lo: row ckl -> 256B contiguous (16 uint4)
        {
            const uint4* srcH = (const uint4*)(g_wbh + chunk*CKC_*COUT_);
            const uint4* srcL = (const uint4*)(g_wbl + chunk*CKC_*COUT_);
            #pragma unroll
            for (int i = 0; i < 4; ++i) {
                int idx = tid + (i << 8);       // 0..1023
                int row = idx >> 4, col = idx & 15;
                *(uint4*)((char*)b_hi + row*(B_LD*2) + col*16) = srcH[idx];
                *(uint4*)((char*)b_lo + row*(B_LD*2) + col*16) = srcL[idx];
            }
        }

        // gather + convert into A hi/lo [128px][64ck], ld=72
        #pragma unroll
        for (int it = 0; it < 8; ++it) {
            int p = (wid << 4) + (it << 1) + pl;     // 0..127
            const int*   cb = cb_s + ((k << 7) + p)*4;
            const float* cw = cw_s + ((k << 7) + p)*4;
            float a0 = 0.f, a1 = 0.f, a2 = 0.f, a3 = 0.f;
            #pragma unroll
            for (int j = 0; j < 4; ++j) {
                float w = cw[j];
                float4 t = *(const float4*)(g_nhwc + cb[j] + c0 + (quad << 2));
                a0 = fmaf(w, t.x, a0);
                a1 = fmaf(w, t.y, a1);
                a2 = fmaf(w, t.z, a2);
                a3 = fmaf(w, t.w, a3);
            }
            __nv_bfloat16 h0 = __float2bfloat16(a0);
            __nv_bfloat16 h1 = __float2bfloat16(a1);
            __nv_bfloat16 h2 = __float2bfloat16(a2);
            __nv_bfloat16 h3 = __float2bfloat16(a3);
            __nv_bfloat16 l0 = __float2bfloat16(a0 - __bfloat162float(h0));
            __nv_bfloat16 l1 = __float2bfloat16(a1 - __bfloat162float(h1));
            __nv_bfloat16 l2 = __float2bfloat16(a2 - __bfloat162float(h2));
            __nv_bfloat16 l3 = __float2bfloat16(a3 - __bfloat162float(h3));
            uint32_t hp0, hp1, lp0, lp1;
            {
                __nv_bfloat162 t0(h0, h1), t1(h2, h3), t2(l0, l1), t3(l2, l3);
                hp0 = *(uint32_t*)&t0; hp1 = *(uint32_t*)&t1;
                lp0 = *(uint32_t*)&t2; lp1 = *(uint32_t*)&t3;
            }
            uint32_t off = (uint32_t)(p*(A_LD*2) + quad*8);
            *(uint2*)((char*)a_hi + off) = make_uint2(hp0, hp1);
            *(uint2*)((char*)a_lo + off) = make_uint2(lp0, lp1);
        }
        __syncthreads();

        // WMMA: 4 k-tiles; A frags (2m, hi+lo) held across the 4-n loop
        #pragma unroll
        for (int kt = 0; kt < 4; ++kt) {
            wmma::fragment<wmma::matrix_a, 16, 16, 16, __nv_bfloat16, wmma::row_major> fah[2], fal[2];
            #pragma unroll
            for (int m = 0; m < 2; ++m) {
                int row = mtile2*32 + m*16;
                wmma::load_matrix_sync(fah[m], a_hi + row*A_LD + kt*16, A_LD);
                wmma::load_matrix_sync(fal[m], a_lo + row*A_LD + kt*16, A_LD);
            }
            #pragma unroll
            for (int nt = 0; nt < 4; ++nt) {
                wmma::fragment<wmma::matrix_b, 16, 16, 16, __nv_bfloat16, wmma::row_major> fbh, fbl;
                int ncol = (ntile0 + nt) * 16;
                wmma::load_matrix_sync(fbh, b_hi + kt*16*B_LD + ncol, B_LD);
                wmma::load_matrix_sync(fbl, b_lo + kt*16*B_LD + ncol, B_LD);
                #pragma unroll
                for (int m = 0; m < 2; ++m) {
                    wmma::mma_sync(accf[m][nt], fah[m], fbh, accf[m][nt]);
                    wmma::mma_sync(accf[m][nt], fah[m], fbl, accf[m][nt]);
                    wmma::mma_sync(accf[m][nt], fal[m], fbh, accf[m][nt]);
                }
            }
        }
    }

    // ---- Epilogue: C frags -> smem (alias), bias, NCHW stores ----
    __syncthreads();
    #pragma unroll
    for (int m = 0; m < 2; ++m)
        #pragma unroll
        for (int nt = 0; nt < 4; ++nt)
            wmma::store_matrix_sync(c_s + (mtile2*32 + m*16)*C_LD + (ntile0 + nt)*16,
                                    accf[m][nt], C_LD, wmma::mem_row_major);
    __syncthreads();

    {
        int oc = tid >> 1;
        int ph = (tid & 1) << 6;            // px half: 0 or 64
        float bv = __ldg(b_dc + oc);
        float* ob = out + ((b*COUT_ + oc)*H_ + y)*W_;
        #pragma unroll
        for (int j = 0; j < 16; ++j) {
            int px = ph + (j << 2);
            float4 v;
            v.x = c_s[(px+0)*C_LD + oc] + bv;
            v.y = c_s[(px+1)*C_LD + oc] + bv;
            v.z = c_s[(px+2)*C_LD + oc] + bv;
            v.w = c_s[(px+3)*C_LD + oc] + bv;
            *(float4*)(ob + px) = v;
        }
    }
}

// ---------------------------------------------------------------------------
extern "C" void kernel_launch(void* const* d_in, const int* in_sizes, int n_in,
                              void* d_out, int out_size) {
    const float* inp   = (const float*)d_in[0];
    const float* feat  = (const float*)d_in[1];
    const float* w_off = (const float*)d_in[2];
    const float* b_off = (const float*)d_in[3];
    const float* w_dc  = (const float*)d_in[4];
    const float* b_dc  = (const float*)d_in[5];
    float* out = (float*)d_out;

    cudaFuncSetAttribute(k_dcn, cudaFuncAttributeMaxDynamicSharedMemorySize, SMEM_DCN);

    k_transpose<<<dim3(HW_/32, CIN_/32, B_), dim3(32, 8)>>>(inp);
    k_wprep<<<(COUT_*CK_ + 255)/256, 256>>>(w_dc);
    k_offconv<<<B_*(H_/2), 256>>>(feat, w_off, b_off);
    k_dcn<<<B_*H_, 256, SMEM_DCN>>>(b_dc, out);
}